// round 1
// baseline (speedup 1.0000x reference)
#include <cuda_runtime.h>
#include <math.h>

#define DIMN  1024
#define NH    16
#define HD    64
#define BATCH 2
#define SEQ   2048
#define MROWS (BATCH*SEQ)   // 4096

// ---------------- scratch (device globals; no allocations allowed) ----------
__device__ float g_qlin[MROWS*DIMN];
__device__ float g_klin[MROWS*DIMN];
__device__ float g_qt[MROWS*DIMN];   // [B,H,S,hd]
__device__ float g_kt[MROWS*DIMN];   // [B,H,S,hd]
__device__ float g_vt[MROWS*DIMN];   // [B,H,S,hd]
__device__ float g_o [MROWS*DIMN];   // [B,S,D]

// ---------------- SGEMM: C[M,N] = A[M,K] @ W[N,K]^T  (M=4096,N=1024,K=1024) --
#define BM 128
#define BN 128
#define BK 8
#define TM 8
#define TN 8

__device__ __forceinline__ void gemm_body(const float* __restrict__ A,
                                          const float* __restrict__ W,
                                          float* __restrict__ C,
                                          int vmode)
{
    __shared__ float As[BK][BM];
    __shared__ float Bs[BK][BN];
    const int tid  = threadIdx.x;
    const int row0 = blockIdx.y * BM;
    const int col0 = blockIdx.x * BN;
    const int tRow = (tid >> 4) * TM;
    const int tCol = (tid & 15) * TN;
    const int ldRow = tid >> 1;        // 0..127
    const int ldCol = (tid & 1) * 4;   // 0 or 4

    const float* Ap = A + (size_t)(row0 + ldRow) * DIMN + ldCol;
    const float* Wp = W + (size_t)(col0 + ldRow) * DIMN + ldCol;

    float acc[TM][TN];
    #pragma unroll
    for (int i = 0; i < TM; i++)
        #pragma unroll
        for (int j = 0; j < TN; j++) acc[i][j] = 0.0f;

    for (int k0 = 0; k0 < DIMN; k0 += BK) {
        float4 av = *reinterpret_cast<const float4*>(Ap + k0);
        float4 wv = *reinterpret_cast<const float4*>(Wp + k0);
        As[ldCol+0][ldRow] = av.x; As[ldCol+1][ldRow] = av.y;
        As[ldCol+2][ldRow] = av.z; As[ldCol+3][ldRow] = av.w;
        Bs[ldCol+0][ldRow] = wv.x; Bs[ldCol+1][ldRow] = wv.y;
        Bs[ldCol+2][ldRow] = wv.z; Bs[ldCol+3][ldRow] = wv.w;
        __syncthreads();
        #pragma unroll
        for (int kk = 0; kk < BK; kk++) {
            float4 a0 = *reinterpret_cast<const float4*>(&As[kk][tRow]);
            float4 a1 = *reinterpret_cast<const float4*>(&As[kk][tRow+4]);
            float4 b0 = *reinterpret_cast<const float4*>(&Bs[kk][tCol]);
            float4 b1 = *reinterpret_cast<const float4*>(&Bs[kk][tCol+4]);
            float ra[TM] = {a0.x,a0.y,a0.z,a0.w,a1.x,a1.y,a1.z,a1.w};
            float rb[TN] = {b0.x,b0.y,b0.z,b0.w,b1.x,b1.y,b1.z,b1.w};
            #pragma unroll
            for (int i = 0; i < TM; i++)
                #pragma unroll
                for (int j = 0; j < TN; j++)
                    acc[i][j] = fmaf(ra[i], rb[j], acc[i][j]);
        }
        __syncthreads();
    }

    if (!vmode) {
        #pragma unroll
        for (int i = 0; i < TM; i++) {
            float4 v0 = make_float4(acc[i][0], acc[i][1], acc[i][2], acc[i][3]);
            float4 v1 = make_float4(acc[i][4], acc[i][5], acc[i][6], acc[i][7]);
            float* cp = C + (size_t)(row0 + tRow + i) * DIMN + col0 + tCol;
            *reinterpret_cast<float4*>(cp)     = v0;
            *reinterpret_cast<float4*>(cp + 4) = v1;
        }
    } else {
        // write transposed into [B,H,S,hd] (used for V)
        #pragma unroll
        for (int i = 0; i < TM; i++) {
            int r = row0 + tRow + i;
            int b = r >> 11, s = r & (SEQ-1);
            #pragma unroll
            for (int j = 0; j < TN; j++) {
                int c = col0 + tCol + j;
                int h = c >> 6, d = c & (HD-1);
                C[(((size_t)(b*NH + h))*SEQ + s)*HD + d] = acc[i][j];
            }
        }
    }
}

__global__ __launch_bounds__(256)
void qkv_gemm(const float* __restrict__ x,
              const float* __restrict__ Wq,
              const float* __restrict__ Wk,
              const float* __restrict__ Wv)
{
    if (blockIdx.z == 0)      gemm_body(x, Wq, g_qlin, 0);
    else if (blockIdx.z == 1) gemm_body(x, Wk, g_klin, 0);
    else                      gemm_body(x, Wv, g_vt,   1);
}

__global__ __launch_bounds__(256)
void out_gemm(const float* __restrict__ Wo, float* __restrict__ C)
{
    gemm_body(g_o, Wo, C, 0);
}

// ---------------- RoPE + transpose to [B,H,S,hd] ----------------------------
__global__ void rope_transpose()
{
    int idx = blockIdx.x * blockDim.x + threadIdx.x;
    if (idx >= BATCH*SEQ*NH*(HD/2)) return;
    int d2 = idx & 31;
    int h  = (idx >> 5) & (NH-1);
    int s  = (idx >> 9) & (SEQ-1);
    int b  = idx >> 20;

    float inv = 1.0f / powf(10000.0f, (float)(2*d2) * (1.0f/(float)HD));
    float ang = (float)s * inv;
    float c  = cosf(ang);
    float sn = sinf(ang);

    size_t src = ((size_t)(b*SEQ + s))*DIMN + h*HD;
    size_t dst = (((size_t)(b*NH + h))*SEQ + s)*HD;

    float q1 = g_qlin[src + d2], q2 = g_qlin[src + d2 + 32];
    g_qt[dst + d2]      = q1*c - q2*sn;
    g_qt[dst + d2 + 32] = q2*c + q1*sn;

    float k1 = g_klin[src + d2], k2 = g_klin[src + d2 + 32];
    g_kt[dst + d2]      = k1*c - k2*sn;
    g_kt[dst + d2 + 32] = k2*c + k1*sn;
}

// ---------------- Flash attention (causal), fp32 ----------------------------
#define BQ  64
#define BKV 32

__global__ __launch_bounds__(256)
void flash_attn()
{
    const int iq = blockIdx.x;          // q tile
    const int h  = blockIdx.y;
    const int b  = blockIdx.z;
    const int q0 = iq * BQ;

    __shared__ float Qs[BQ][HD+1];       // 64 x 65
    __shared__ float Ks[BKV][HD+1];      // 32 x 65
    __shared__ float Vs[BKV][HD+1];      // 32 x 65
    __shared__ float Ps[BQ][BKV+1];      // 64 x 33

    const int tid = threadIdx.x;
    const int tx  = tid & 15;            // 0..15
    const int ty  = tid >> 4;            // 0..15

    // load Q tile
    const float* Qg = g_qt + (((size_t)(b*NH + h))*SEQ + q0)*HD;
    for (int i = tid; i < BQ*HD/4; i += 256) {
        float4 v = reinterpret_cast<const float4*>(Qg)[i];
        int r = (i*4) / HD, c = (i*4) & (HD-1);
        Qs[r][c+0]=v.x; Qs[r][c+1]=v.y; Qs[r][c+2]=v.z; Qs[r][c+3]=v.w;
    }

    float m[4], l[4], o[4][4];
    #pragma unroll
    for (int i = 0; i < 4; i++) {
        m[i] = -INFINITY; l[i] = 0.0f;
        #pragma unroll
        for (int j = 0; j < 4; j++) o[i][j] = 0.0f;
    }

    const int nkv = (iq + 1) * (BQ / BKV);   // causal: tiles up to and incl. diag
    const float* Kbase = g_kt + ((size_t)(b*NH + h))*SEQ*HD;
    const float* Vbase = g_vt + ((size_t)(b*NH + h))*SEQ*HD;

    for (int t = 0; t < nkv; t++) {
        const int kv0 = t * BKV;
        __syncthreads();   // prior PV reads of Ks/Vs/Ps done
        for (int i = tid; i < BKV*HD/4; i += 256) {
            float4 kv = reinterpret_cast<const float4*>(Kbase + (size_t)kv0*HD)[i];
            float4 vv = reinterpret_cast<const float4*>(Vbase + (size_t)kv0*HD)[i];
            int r = (i*4) / HD, c = (i*4) & (HD-1);
            Ks[r][c+0]=kv.x; Ks[r][c+1]=kv.y; Ks[r][c+2]=kv.z; Ks[r][c+3]=kv.w;
            Vs[r][c+0]=vv.x; Vs[r][c+1]=vv.y; Vs[r][c+2]=vv.z; Vs[r][c+3]=vv.w;
        }
        __syncthreads();

        // S = Q K^T : rows ty*4+i, cols tx*2+j
        float sc[4][2] = {{0,0},{0,0},{0,0},{0,0}};
        #pragma unroll 8
        for (int d = 0; d < HD; d++) {
            float qv[4], kk[2];
            #pragma unroll
            for (int i = 0; i < 4; i++) qv[i] = Qs[ty*4+i][d];
            #pragma unroll
            for (int j = 0; j < 2; j++) kk[j] = Ks[tx*2+j][d];
            #pragma unroll
            for (int i = 0; i < 4; i++)
                #pragma unroll
                for (int j = 0; j < 2; j++)
                    sc[i][j] = fmaf(qv[i], kk[j], sc[i][j]);
        }

        // scale + causal mask
        #pragma unroll
        for (int i = 0; i < 4; i++) {
            int qg = q0 + ty*4 + i;
            #pragma unroll
            for (int j = 0; j < 2; j++) {
                int kg = kv0 + tx*2 + j;
                sc[i][j] = (kg > qg) ? -1e30f : sc[i][j] * 0.125f;
            }
        }

        // online softmax
        #pragma unroll
        for (int i = 0; i < 4; i++) {
            float tmax = fmaxf(sc[i][0], sc[i][1]);
            #pragma unroll
            for (int msk = 1; msk <= 8; msk <<= 1)
                tmax = fmaxf(tmax, __shfl_xor_sync(0xffffffffu, tmax, msk));
            float mnew = fmaxf(m[i], tmax);
            float p0 = expf(sc[i][0] - mnew);
            float p1 = expf(sc[i][1] - mnew);
            float psum = p0 + p1;
            #pragma unroll
            for (int msk = 1; msk <= 8; msk <<= 1)
                psum += __shfl_xor_sync(0xffffffffu, psum, msk);
            float alpha = expf(m[i] - mnew);
            l[i] = l[i]*alpha + psum;
            m[i] = mnew;
            #pragma unroll
            for (int j = 0; j < 4; j++) o[i][j] *= alpha;
            Ps[ty*4+i][tx*2+0] = p0;
            Ps[ty*4+i][tx*2+1] = p1;
        }
        __syncthreads();

        // O += P @ V : dims tx*4+j
        #pragma unroll 4
        for (int c = 0; c < BKV; c++) {
            float pv[4], vv[4];
            #pragma unroll
            for (int i = 0; i < 4; i++) pv[i] = Ps[ty*4+i][c];
            #pragma unroll
            for (int j = 0; j < 4; j++) vv[j] = Vs[c][tx*4+j];
            #pragma unroll
            for (int i = 0; i < 4; i++)
                #pragma unroll
                for (int j = 0; j < 4; j++)
                    o[i][j] = fmaf(pv[i], vv[j], o[i][j]);
        }
    }

    // write O to [B,S,D]
    #pragma unroll
    for (int i = 0; i < 4; i++) {
        float invl = 1.0f / l[i];
        size_t base = ((size_t)(b*SEQ + q0 + ty*4 + i))*DIMN + h*HD + tx*4;
        #pragma unroll
        for (int j = 0; j < 4; j++)
            g_o[base + j] = o[i][j] * invl;
    }
}

// ---------------- launch ----------------------------------------------------
extern "C" void kernel_launch(void* const* d_in, const int* in_sizes, int n_in,
                              void* d_out, int out_size)
{
    const float* x  = (const float*)d_in[0];
    const float* Wq = (const float*)d_in[1];
    const float* Wk = (const float*)d_in[2];
    const float* Wv = (const float*)d_in[3];
    const float* Wo = (const float*)d_in[4];
    float* out = (float*)d_out;

    dim3 gqkv(DIMN/BN, MROWS/BM, 3);
    qkv_gemm<<<gqkv, 256>>>(x, Wq, Wk, Wv);

    int nrope = BATCH*SEQ*NH*(HD/2);
    rope_transpose<<<(nrope + 255)/256, 256>>>();

    dim3 gfl(SEQ/BQ, NH, BATCH);
    flash_attn<<<gfl, 256>>>();

    dim3 gout(DIMN/BN, MROWS/BM);
    out_gemm<<<gout, 256>>>(Wo, out);
}

// round 2
// speedup vs baseline: 1.4067x; 1.4067x over previous
#include <cuda_runtime.h>
#include <cuda_bf16.h>
#include <math.h>

#define DIMN  1024
#define NH    16
#define HD    64
#define BATCH 2
#define SEQ   2048
#define MROWS (BATCH*SEQ)   // 4096

// ---------------- scratch (device globals; no allocations allowed) ----------
__device__ float g_qlin[MROWS*DIMN];
__device__ float g_klin[MROWS*DIMN];
__device__ float g_qt[MROWS*DIMN];   // [B,H,S,hd]
__device__ float g_kt[MROWS*DIMN];   // [B,H,S,hd]
__device__ float g_vt[MROWS*DIMN];   // [B,H,S,hd]
__device__ float g_o [MROWS*DIMN];   // [B,S,D]

// bf16 split (hi/lo) versions
__device__ __nv_bfloat16 g_xhi[MROWS*DIMN];
__device__ __nv_bfloat16 g_xlo[MROWS*DIMN];
__device__ __nv_bfloat16 g_ohi[MROWS*DIMN];
__device__ __nv_bfloat16 g_olo[MROWS*DIMN];
__device__ __nv_bfloat16 g_whi[4][DIMN*DIMN];
__device__ __nv_bfloat16 g_wlo[4][DIMN*DIMN];

// ---------------- fp32 -> bf16 hi/lo split ----------------------------------
__global__ __launch_bounds__(256)
void f32_split(const float* __restrict__ src,
               __nv_bfloat16* __restrict__ hi,
               __nv_bfloat16* __restrict__ lo, int n4)
{
    int i = blockIdx.x * blockDim.x + threadIdx.x;
    if (i >= n4) return;
    float4 v = reinterpret_cast<const float4*>(src)[i];
    float f[4] = {v.x, v.y, v.z, v.w};
    unsigned short ph[4], pl[4];
#pragma unroll
    for (int j = 0; j < 4; j++) {
        __nv_bfloat16 h = __float2bfloat16(f[j]);
        __nv_bfloat16 l = __float2bfloat16(f[j] - __bfloat162float(h));
        ph[j] = *reinterpret_cast<unsigned short*>(&h);
        pl[j] = *reinterpret_cast<unsigned short*>(&l);
    }
    reinterpret_cast<ushort4*>(hi)[i] = make_ushort4(ph[0], ph[1], ph[2], ph[3]);
    reinterpret_cast<ushort4*>(lo)[i] = make_ushort4(pl[0], pl[1], pl[2], pl[3]);
}

// ---------------- tensor-core GEMM: C[M,N] = A[M,K] @ W[N,K]^T ---------------
// split-bf16: A = Ah + Al, W = Wh + Wl;  C = Ah*Wh + Ah*Wl + Al*Wh (fp32 acc)
// block tile 128x128, 8 warps of 64x32, mma m16n8k16, cp.async 2-stage.

__device__ __forceinline__ unsigned int smem_u32(const void* p) {
    return (unsigned int)__cvta_generic_to_shared(p);
}
__device__ __forceinline__ void cp16(unsigned int s, const void* g) {
    asm volatile("cp.async.cg.shared.global [%0], [%1], 16;\n" :: "r"(s), "l"(g));
}
__device__ __forceinline__ void cp_commit() {
    asm volatile("cp.async.commit_group;\n");
}
__device__ __forceinline__ void cp_wait1() {
    asm volatile("cp.async.wait_group 1;\n");
}
__device__ __forceinline__ void ldmx4(unsigned int addr, unsigned int& r0, unsigned int& r1,
                                      unsigned int& r2, unsigned int& r3) {
    asm volatile("ldmatrix.sync.aligned.m8n8.x4.shared.b16 {%0,%1,%2,%3}, [%4];\n"
                 : "=r"(r0), "=r"(r1), "=r"(r2), "=r"(r3) : "r"(addr));
}
__device__ __forceinline__ void mma16816(float* c, const unsigned int* a,
                                         unsigned int b0, unsigned int b1) {
    asm volatile("mma.sync.aligned.m16n8k16.row.col.f32.bf16.bf16.f32 "
                 "{%0,%1,%2,%3}, {%4,%5,%6,%7}, {%8,%9}, {%0,%1,%2,%3};\n"
                 : "+f"(c[0]), "+f"(c[1]), "+f"(c[2]), "+f"(c[3])
                 : "r"(a[0]), "r"(a[1]), "r"(a[2]), "r"(a[3]), "r"(b0), "r"(b1));
}

__device__ __forceinline__ void gemm_mma_body(const __nv_bfloat16* __restrict__ Ah,
                                              const __nv_bfloat16* __restrict__ Al,
                                              const __nv_bfloat16* __restrict__ Bh,
                                              const __nv_bfloat16* __restrict__ Bl,
                                              float* __restrict__ C, int vmode)
{
    __shared__ __align__(128) __nv_bfloat16 sA[2][2][128][16];
    __shared__ __align__(128) __nv_bfloat16 sB[2][2][128][16];

    const int tid   = threadIdx.x;
    const int lane  = tid & 31;
    const int warp  = tid >> 5;
    const int wm    = warp >> 2;          // 0..1
    const int wn    = warp & 3;           // 0..3
    const int row0  = blockIdx.y * 128;
    const int col0  = blockIdx.x * 128;

    // loader mapping: one 16B chunk per (matrix, row)
    const int lrow = tid >> 1;            // 0..127
    const int lch  = tid & 1;             // 0..1
    const int lpc  = lch ^ ((lrow >> 2) & 1);
    const size_t aoff = (size_t)(row0 + lrow) * DIMN + lch * 8;
    const size_t boff = (size_t)(col0 + lrow) * DIMN + lch * 8;

    float acc[4][4][4];
#pragma unroll
    for (int i = 0; i < 4; i++)
#pragma unroll
        for (int j = 0; j < 4; j++)
#pragma unroll
            for (int k = 0; k < 4; k++) acc[i][j][k] = 0.0f;

    // precompute ldmatrix smem addresses (stage-0 base; stage stride constant)
    const unsigned int stg = (unsigned int)(2 * 128 * 16 * sizeof(__nv_bfloat16)); // 8KB per stage

    // A frag addr per m-tile
    unsigned int aAddr[4][2], bAddr[2][2]; // [tile][hi/lo]
#pragma unroll
    for (int mt = 0; mt < 4; mt++) {
        int r  = wm * 64 + mt * 16 + (lane & 15);
        int ch = lane >> 4;
        int pc = ch ^ ((r >> 2) & 1);
        aAddr[mt][0] = smem_u32(&sA[0][0][r][pc * 8]);
        aAddr[mt][1] = smem_u32(&sA[0][1][r][pc * 8]);
    }
#pragma unroll
    for (int p = 0; p < 2; p++) {
        int grp = lane >> 3;
        int r   = wn * 32 + p * 16 + (grp >> 1) * 8 + (lane & 7);
        int ch  = grp & 1;
        int pc  = ch ^ ((r >> 2) & 1);
        bAddr[p][0] = smem_u32(&sB[0][0][r][pc * 8]);
        bAddr[p][1] = smem_u32(&sB[0][1][r][pc * 8]);
    }

    // prologue: load stage 0 (k0 = 0)
    {
        unsigned int sa0 = smem_u32(&sA[0][0][lrow][lpc * 8]);
        unsigned int sa1 = smem_u32(&sA[0][1][lrow][lpc * 8]);
        unsigned int sb0 = smem_u32(&sB[0][0][lrow][lpc * 8]);
        unsigned int sb1 = smem_u32(&sB[0][1][lrow][lpc * 8]);
        cp16(sa0, Ah + aoff); cp16(sa1, Al + aoff);
        cp16(sb0, Bh + boff); cp16(sb1, Bl + boff);
        cp_commit();
    }

    const int KT = DIMN / 16;  // 64
    for (int kt = 0; kt < KT; kt++) {
        int cur = kt & 1;
        if (kt + 1 < KT) {
            int nxt = (kt + 1) & 1;
            size_t ko = (size_t)(kt + 1) * 16;
            unsigned int sa0 = smem_u32(&sA[nxt][0][lrow][lpc * 8]);
            unsigned int sa1 = smem_u32(&sA[nxt][1][lrow][lpc * 8]);
            unsigned int sb0 = smem_u32(&sB[nxt][0][lrow][lpc * 8]);
            unsigned int sb1 = smem_u32(&sB[nxt][1][lrow][lpc * 8]);
            cp16(sa0, Ah + aoff + ko); cp16(sa1, Al + aoff + ko);
            cp16(sb0, Bh + boff + ko); cp16(sb1, Bl + boff + ko);
        }
        cp_commit();
        cp_wait1();
        __syncthreads();

        unsigned int coff = cur * stg;
        unsigned int ah[4][4], al[4][4], bh[2][4], bl[2][4];
#pragma unroll
        for (int mt = 0; mt < 4; mt++) {
            ldmx4(aAddr[mt][0] + coff, ah[mt][0], ah[mt][1], ah[mt][2], ah[mt][3]);
            ldmx4(aAddr[mt][1] + coff, al[mt][0], al[mt][1], al[mt][2], al[mt][3]);
        }
#pragma unroll
        for (int p = 0; p < 2; p++) {
            ldmx4(bAddr[p][0] + coff, bh[p][0], bh[p][1], bh[p][2], bh[p][3]);
            ldmx4(bAddr[p][1] + coff, bl[p][0], bl[p][1], bl[p][2], bl[p][3]);
        }
#pragma unroll
        for (int mt = 0; mt < 4; mt++) {
#pragma unroll
            for (int nt = 0; nt < 4; nt++) {
                int p = nt >> 1, s = nt & 1;
                mma16816(acc[mt][nt], ah[mt], bh[p][2*s], bh[p][2*s+1]); // hi*hi
                mma16816(acc[mt][nt], ah[mt], bl[p][2*s], bl[p][2*s+1]); // hi*lo
                mma16816(acc[mt][nt], al[mt], bh[p][2*s], bh[p][2*s+1]); // lo*hi
            }
        }
        __syncthreads();
    }

    // epilogue
    if (!vmode) {
#pragma unroll
        for (int mt = 0; mt < 4; mt++) {
            int r = row0 + wm * 64 + mt * 16 + (lane >> 2);
#pragma unroll
            for (int nt = 0; nt < 4; nt++) {
                int c = col0 + wn * 32 + nt * 8 + (lane & 3) * 2;
                *reinterpret_cast<float2*>(&C[(size_t)r * DIMN + c]) =
                    make_float2(acc[mt][nt][0], acc[mt][nt][1]);
                *reinterpret_cast<float2*>(&C[(size_t)(r + 8) * DIMN + c]) =
                    make_float2(acc[mt][nt][2], acc[mt][nt][3]);
            }
        }
    } else {
        // scatter transposed into [B,H,S,hd]
#pragma unroll
        for (int mt = 0; mt < 4; mt++) {
            int r = row0 + wm * 64 + mt * 16 + (lane >> 2);
#pragma unroll
            for (int nt = 0; nt < 4; nt++) {
                int c = col0 + wn * 32 + nt * 8 + (lane & 3) * 2;
#pragma unroll
                for (int e = 0; e < 4; e++) {
                    int rr = r + (e >> 1) * 8;
                    int cc = c + (e & 1);
                    int b = rr >> 11, s = rr & (SEQ-1);
                    int h = cc >> 6,  d = cc & (HD-1);
                    C[(((size_t)(b*NH + h))*SEQ + s)*HD + d] = acc[mt][nt][e];
                }
            }
        }
    }
}

__global__ __launch_bounds__(256)
void qkv_gemm_mma(const __nv_bfloat16* __restrict__ xhi,
                  const __nv_bfloat16* __restrict__ xlo)
{
    int z = blockIdx.z;
    if (z == 0)      gemm_mma_body(xhi, xlo, g_whi[0], g_wlo[0], g_qlin, 0);
    else if (z == 1) gemm_mma_body(xhi, xlo, g_whi[1], g_wlo[1], g_klin, 0);
    else             gemm_mma_body(xhi, xlo, g_whi[2], g_wlo[2], g_vt,   1);
}

__global__ __launch_bounds__(256)
void out_gemm_mma(float* __restrict__ C)
{
    gemm_mma_body(g_ohi, g_olo, g_whi[3], g_wlo[3], C, 0);
}

// ---------------- RoPE + transpose to [B,H,S,hd] ----------------------------
__global__ void rope_transpose()
{
    int idx = blockIdx.x * blockDim.x + threadIdx.x;
    if (idx >= BATCH*SEQ*NH*(HD/2)) return;
    int d2 = idx & 31;
    int h  = (idx >> 5) & (NH-1);
    int s  = (idx >> 9) & (SEQ-1);
    int b  = idx >> 20;

    float inv = 1.0f / powf(10000.0f, (float)(2*d2) * (1.0f/(float)HD));
    float ang = (float)s * inv;
    float c  = cosf(ang);
    float sn = sinf(ang);

    size_t src = ((size_t)(b*SEQ + s))*DIMN + h*HD;
    size_t dst = (((size_t)(b*NH + h))*SEQ + s)*HD;

    float q1 = g_qlin[src + d2], q2 = g_qlin[src + d2 + 32];
    g_qt[dst + d2]      = q1*c - q2*sn;
    g_qt[dst + d2 + 32] = q2*c + q1*sn;

    float k1 = g_klin[src + d2], k2 = g_klin[src + d2 + 32];
    g_kt[dst + d2]      = k1*c - k2*sn;
    g_kt[dst + d2 + 32] = k2*c + k1*sn;
}

// ---------------- Flash attention (causal), fp32 ----------------------------
#define BQ  64
#define BKV 32

__global__ __launch_bounds__(256)
void flash_attn()
{
    const int iq = blockIdx.x;
    const int h  = blockIdx.y;
    const int b  = blockIdx.z;
    const int q0 = iq * BQ;

    __shared__ float Qs[BQ][HD+1];
    __shared__ float Ks[BKV][HD+1];
    __shared__ float Vs[BKV][HD+1];
    __shared__ float Ps[BQ][BKV+1];

    const int tid = threadIdx.x;
    const int tx  = tid & 15;
    const int ty  = tid >> 4;

    const float* Qg = g_qt + (((size_t)(b*NH + h))*SEQ + q0)*HD;
    for (int i = tid; i < BQ*HD/4; i += 256) {
        float4 v = reinterpret_cast<const float4*>(Qg)[i];
        int r = (i*4) / HD, c = (i*4) & (HD-1);
        Qs[r][c+0]=v.x; Qs[r][c+1]=v.y; Qs[r][c+2]=v.z; Qs[r][c+3]=v.w;
    }

    float m[4], l[4], o[4][4];
#pragma unroll
    for (int i = 0; i < 4; i++) {
        m[i] = -INFINITY; l[i] = 0.0f;
#pragma unroll
        for (int j = 0; j < 4; j++) o[i][j] = 0.0f;
    }

    const int nkv = (iq + 1) * (BQ / BKV);
    const float* Kbase = g_kt + ((size_t)(b*NH + h))*SEQ*HD;
    const float* Vbase = g_vt + ((size_t)(b*NH + h))*SEQ*HD;

    for (int t = 0; t < nkv; t++) {
        const int kv0 = t * BKV;
        __syncthreads();
        for (int i = tid; i < BKV*HD/4; i += 256) {
            float4 kv = reinterpret_cast<const float4*>(Kbase + (size_t)kv0*HD)[i];
            float4 vv = reinterpret_cast<const float4*>(Vbase + (size_t)kv0*HD)[i];
            int r = (i*4) / HD, c = (i*4) & (HD-1);
            Ks[r][c+0]=kv.x; Ks[r][c+1]=kv.y; Ks[r][c+2]=kv.z; Ks[r][c+3]=kv.w;
            Vs[r][c+0]=vv.x; Vs[r][c+1]=vv.y; Vs[r][c+2]=vv.z; Vs[r][c+3]=vv.w;
        }
        __syncthreads();

        float sc[4][2] = {{0,0},{0,0},{0,0},{0,0}};
#pragma unroll 8
        for (int d = 0; d < HD; d++) {
            float qv[4], kk[2];
#pragma unroll
            for (int i = 0; i < 4; i++) qv[i] = Qs[ty*4+i][d];
#pragma unroll
            for (int j = 0; j < 2; j++) kk[j] = Ks[tx*2+j][d];
#pragma unroll
            for (int i = 0; i < 4; i++)
#pragma unroll
                for (int j = 0; j < 2; j++)
                    sc[i][j] = fmaf(qv[i], kk[j], sc[i][j]);
        }

#pragma unroll
        for (int i = 0; i < 4; i++) {
            int qg = q0 + ty*4 + i;
#pragma unroll
            for (int j = 0; j < 2; j++) {
                int kg = kv0 + tx*2 + j;
                sc[i][j] = (kg > qg) ? -1e30f : sc[i][j] * 0.125f;
            }
        }

#pragma unroll
        for (int i = 0; i < 4; i++) {
            float tmax = fmaxf(sc[i][0], sc[i][1]);
#pragma unroll
            for (int msk = 1; msk <= 8; msk <<= 1)
                tmax = fmaxf(tmax, __shfl_xor_sync(0xffffffffu, tmax, msk));
            float mnew = fmaxf(m[i], tmax);
            float p0 = expf(sc[i][0] - mnew);
            float p1 = expf(sc[i][1] - mnew);
            float psum = p0 + p1;
#pragma unroll
            for (int msk = 1; msk <= 8; msk <<= 1)
                psum += __shfl_xor_sync(0xffffffffu, psum, msk);
            float alpha = expf(m[i] - mnew);
            l[i] = l[i]*alpha + psum;
            m[i] = mnew;
#pragma unroll
            for (int j = 0; j < 4; j++) o[i][j] *= alpha;
            Ps[ty*4+i][tx*2+0] = p0;
            Ps[ty*4+i][tx*2+1] = p1;
        }
        __syncthreads();

#pragma unroll 4
        for (int c = 0; c < BKV; c++) {
            float pv[4], vv[4];
#pragma unroll
            for (int i = 0; i < 4; i++) pv[i] = Ps[ty*4+i][c];
#pragma unroll
            for (int j = 0; j < 4; j++) vv[j] = Vs[c][tx*4+j];
#pragma unroll
            for (int i = 0; i < 4; i++)
#pragma unroll
                for (int j = 0; j < 4; j++)
                    o[i][j] = fmaf(pv[i], vv[j], o[i][j]);
        }
    }

#pragma unroll
    for (int i = 0; i < 4; i++) {
        float invl = 1.0f / l[i];
        size_t base = ((size_t)(b*SEQ + q0 + ty*4 + i))*DIMN + h*HD + tx*4;
#pragma unroll
        for (int j = 0; j < 4; j++)
            g_o[base + j] = o[i][j] * invl;
    }
}

// ---------------- launch ----------------------------------------------------
extern "C" void kernel_launch(void* const* d_in, const int* in_sizes, int n_in,
                              void* d_out, int out_size)
{
    const float* x  = (const float*)d_in[0];
    const float* Wq = (const float*)d_in[1];
    const float* Wk = (const float*)d_in[2];
    const float* Wv = (const float*)d_in[3];
    const float* Wo = (const float*)d_in[4];
    float* out = (float*)d_out;

    __nv_bfloat16 *xhi, *xlo, *ohi, *olo, *whi, *wlo;
    float *go;
    cudaGetSymbolAddress((void**)&xhi, g_xhi);
    cudaGetSymbolAddress((void**)&xlo, g_xlo);
    cudaGetSymbolAddress((void**)&ohi, g_ohi);
    cudaGetSymbolAddress((void**)&olo, g_olo);
    cudaGetSymbolAddress((void**)&whi, g_whi);
    cudaGetSymbolAddress((void**)&wlo, g_wlo);
    cudaGetSymbolAddress((void**)&go,  g_o);

    const int NW = DIMN * DIMN;   // 1M elems per weight
    const int NX = MROWS * DIMN;  // 4M elems

    // split activations + weights to bf16 hi/lo
    f32_split<<<(NX/4 + 255)/256, 256>>>(x,  xhi, xlo, NX/4);
    f32_split<<<(NW/4 + 255)/256, 256>>>(Wq, whi + 0*(size_t)NW, wlo + 0*(size_t)NW, NW/4);
    f32_split<<<(NW/4 + 255)/256, 256>>>(Wk, whi + 1*(size_t)NW, wlo + 1*(size_t)NW, NW/4);
    f32_split<<<(NW/4 + 255)/256, 256>>>(Wv, whi + 2*(size_t)NW, wlo + 2*(size_t)NW, NW/4);
    f32_split<<<(NW/4 + 255)/256, 256>>>(Wo, whi + 3*(size_t)NW, wlo + 3*(size_t)NW, NW/4);

    dim3 gqkv(DIMN/128, MROWS/128, 3);
    qkv_gemm_mma<<<gqkv, 256>>>(xhi, xlo);

    int nrope = BATCH*SEQ*NH*(HD/2);
    rope_transpose<<<(nrope + 255)/256, 256>>>();

    dim3 gfl(SEQ/BQ, NH, BATCH);
    flash_attn<<<gfl, 256>>>();

    f32_split<<<(NX/4 + 255)/256, 256>>>(go, ohi, olo, NX/4);

    dim3 gout(DIMN/128, MROWS/128);
    out_gemm_mma<<<gout, 256>>>(out);
}

// round 3
// speedup vs baseline: 2.6225x; 1.8644x over previous
#include <cuda_runtime.h>
#include <cuda_bf16.h>
#include <math.h>

#define DIMN  1024
#define NH    16
#define HD    64
#define BATCH 2
#define SEQ   2048
#define MROWS (BATCH*SEQ)   // 4096

// ---------------- scratch (device globals; no allocations allowed) ----------
__device__ float g_qlin[MROWS*DIMN];
__device__ float g_klin[MROWS*DIMN];

__device__ __nv_bfloat16 g_xhi[MROWS*DIMN];
__device__ __nv_bfloat16 g_xlo[MROWS*DIMN];
__device__ __nv_bfloat16 g_ohi[MROWS*DIMN];
__device__ __nv_bfloat16 g_olo[MROWS*DIMN];
__device__ __nv_bfloat16 g_whi[4][DIMN*DIMN];
__device__ __nv_bfloat16 g_wlo[4][DIMN*DIMN];

// attention operands, [B,H,S,hd], bf16 hi/lo
__device__ __nv_bfloat16 g_qthi[MROWS*DIMN];
__device__ __nv_bfloat16 g_qtlo[MROWS*DIMN];
__device__ __nv_bfloat16 g_kthi[MROWS*DIMN];
__device__ __nv_bfloat16 g_ktlo[MROWS*DIMN];
__device__ __nv_bfloat16 g_vthi[MROWS*DIMN];
__device__ __nv_bfloat16 g_vtlo[MROWS*DIMN];

// ---------------- helpers ----------------------------------------------------
__device__ __forceinline__ unsigned int smem_u32(const void* p) {
    return (unsigned int)__cvta_generic_to_shared(p);
}
__device__ __forceinline__ void cp16(unsigned int s, const void* g) {
    asm volatile("cp.async.cg.shared.global [%0], [%1], 16;\n" :: "r"(s), "l"(g));
}
__device__ __forceinline__ void cp_commit() {
    asm volatile("cp.async.commit_group;\n");
}
__device__ __forceinline__ void cp_wait1() {
    asm volatile("cp.async.wait_group 1;\n");
}
__device__ __forceinline__ void cp_wait0() {
    asm volatile("cp.async.wait_group 0;\n");
}
__device__ __forceinline__ void ldmx4(unsigned int addr, unsigned int& r0, unsigned int& r1,
                                      unsigned int& r2, unsigned int& r3) {
    asm volatile("ldmatrix.sync.aligned.m8n8.x4.shared.b16 {%0,%1,%2,%3}, [%4];\n"
                 : "=r"(r0), "=r"(r1), "=r"(r2), "=r"(r3) : "r"(addr));
}
__device__ __forceinline__ void ldmx4t(unsigned int addr, unsigned int& r0, unsigned int& r1,
                                       unsigned int& r2, unsigned int& r3) {
    asm volatile("ldmatrix.sync.aligned.m8n8.x4.trans.shared.b16 {%0,%1,%2,%3}, [%4];\n"
                 : "=r"(r0), "=r"(r1), "=r"(r2), "=r"(r3) : "r"(addr));
}
__device__ __forceinline__ void mma16816(float* c, const unsigned int* a,
                                         unsigned int b0, unsigned int b1) {
    asm volatile("mma.sync.aligned.m16n8k16.row.col.f32.bf16.bf16.f32 "
                 "{%0,%1,%2,%3}, {%4,%5,%6,%7}, {%8,%9}, {%0,%1,%2,%3};\n"
                 : "+f"(c[0]), "+f"(c[1]), "+f"(c[2]), "+f"(c[3])
                 : "r"(a[0]), "r"(a[1]), "r"(a[2]), "r"(a[3]), "r"(b0), "r"(b1));
}
__device__ __forceinline__ unsigned short bfbits(float f) {
    __nv_bfloat16 h = __float2bfloat16(f);
    return *reinterpret_cast<unsigned short*>(&h);
}
__device__ __forceinline__ unsigned int pk2(float a, float b) {
    return (unsigned int)bfbits(a) | ((unsigned int)bfbits(b) << 16);
}
__device__ __forceinline__ float bf2f(unsigned short u) {
    __nv_bfloat16 h = *reinterpret_cast<__nv_bfloat16*>(&u);
    return __bfloat162float(h);
}

// ---------------- fp32 -> bf16 hi/lo split ----------------------------------
__global__ __launch_bounds__(256)
void f32_split(const float* __restrict__ src,
               __nv_bfloat16* __restrict__ hi,
               __nv_bfloat16* __restrict__ lo, int n4)
{
    int i = blockIdx.x * blockDim.x + threadIdx.x;
    if (i >= n4) return;
    float4 v = reinterpret_cast<const float4*>(src)[i];
    float f[4] = {v.x, v.y, v.z, v.w};
    unsigned short ph[4], pl[4];
#pragma unroll
    for (int j = 0; j < 4; j++) {
        ph[j] = bfbits(f[j]);
        pl[j] = bfbits(f[j] - bf2f(ph[j]));
    }
    reinterpret_cast<ushort4*>(hi)[i] = make_ushort4(ph[0], ph[1], ph[2], ph[3]);
    reinterpret_cast<ushort4*>(lo)[i] = make_ushort4(pl[0], pl[1], pl[2], pl[3]);
}

// ---------------- tensor-core GEMM: C[M,N] = A[M,K] @ W[N,K]^T ---------------
__device__ __forceinline__ void gemm_mma_body(const __nv_bfloat16* __restrict__ Ah,
                                              const __nv_bfloat16* __restrict__ Al,
                                              const __nv_bfloat16* __restrict__ Bh,
                                              const __nv_bfloat16* __restrict__ Bl,
                                              float* __restrict__ C, int vmode)
{
    __shared__ __align__(128) __nv_bfloat16 sA[2][2][128][16];
    __shared__ __align__(128) __nv_bfloat16 sB[2][2][128][16];

    const int tid   = threadIdx.x;
    const int lane  = tid & 31;
    const int warp  = tid >> 5;
    const int wm    = warp >> 2;
    const int wn    = warp & 3;
    const int row0  = blockIdx.y * 128;
    const int col0  = blockIdx.x * 128;

    const int lrow = tid >> 1;
    const int lch  = tid & 1;
    const int lpc  = lch ^ ((lrow >> 2) & 1);
    const size_t aoff = (size_t)(row0 + lrow) * DIMN + lch * 8;
    const size_t boff = (size_t)(col0 + lrow) * DIMN + lch * 8;

    float acc[4][4][4];
#pragma unroll
    for (int i = 0; i < 4; i++)
#pragma unroll
        for (int j = 0; j < 4; j++)
#pragma unroll
            for (int k = 0; k < 4; k++) acc[i][j][k] = 0.0f;

    const unsigned int stg = (unsigned int)(2 * 128 * 16 * sizeof(__nv_bfloat16));

    unsigned int aAddr[4][2], bAddr[2][2];
#pragma unroll
    for (int mt = 0; mt < 4; mt++) {
        int r  = wm * 64 + mt * 16 + (lane & 15);
        int ch = lane >> 4;
        int pc = ch ^ ((r >> 2) & 1);
        aAddr[mt][0] = smem_u32(&sA[0][0][r][pc * 8]);
        aAddr[mt][1] = smem_u32(&sA[0][1][r][pc * 8]);
    }
#pragma unroll
    for (int p = 0; p < 2; p++) {
        int grp = lane >> 3;
        int r   = wn * 32 + p * 16 + (grp >> 1) * 8 + (lane & 7);
        int ch  = grp & 1;
        int pc  = ch ^ ((r >> 2) & 1);
        bAddr[p][0] = smem_u32(&sB[0][0][r][pc * 8]);
        bAddr[p][1] = smem_u32(&sB[0][1][r][pc * 8]);
    }

    {
        unsigned int sa0 = smem_u32(&sA[0][0][lrow][lpc * 8]);
        unsigned int sa1 = smem_u32(&sA[0][1][lrow][lpc * 8]);
        unsigned int sb0 = smem_u32(&sB[0][0][lrow][lpc * 8]);
        unsigned int sb1 = smem_u32(&sB[0][1][lrow][lpc * 8]);
        cp16(sa0, Ah + aoff); cp16(sa1, Al + aoff);
        cp16(sb0, Bh + boff); cp16(sb1, Bl + boff);
        cp_commit();
    }

    const int KT = DIMN / 16;
    for (int kt = 0; kt < KT; kt++) {
        int cur = kt & 1;
        if (kt + 1 < KT) {
            int nxt = (kt + 1) & 1;
            size_t ko = (size_t)(kt + 1) * 16;
            unsigned int sa0 = smem_u32(&sA[nxt][0][lrow][lpc * 8]);
            unsigned int sa1 = smem_u32(&sA[nxt][1][lrow][lpc * 8]);
            unsigned int sb0 = smem_u32(&sB[nxt][0][lrow][lpc * 8]);
            unsigned int sb1 = smem_u32(&sB[nxt][1][lrow][lpc * 8]);
            cp16(sa0, Ah + aoff + ko); cp16(sa1, Al + aoff + ko);
            cp16(sb0, Bh + boff + ko); cp16(sb1, Bl + boff + ko);
        }
        cp_commit();
        cp_wait1();
        __syncthreads();

        unsigned int coff = cur * stg;
        unsigned int ah[4][4], al[4][4], bh[2][4], bl[2][4];
#pragma unroll
        for (int mt = 0; mt < 4; mt++) {
            ldmx4(aAddr[mt][0] + coff, ah[mt][0], ah[mt][1], ah[mt][2], ah[mt][3]);
            ldmx4(aAddr[mt][1] + coff, al[mt][0], al[mt][1], al[mt][2], al[mt][3]);
        }
#pragma unroll
        for (int p = 0; p < 2; p++) {
            ldmx4(bAddr[p][0] + coff, bh[p][0], bh[p][1], bh[p][2], bh[p][3]);
            ldmx4(bAddr[p][1] + coff, bl[p][0], bl[p][1], bl[p][2], bl[p][3]);
        }
#pragma unroll
        for (int mt = 0; mt < 4; mt++) {
#pragma unroll
            for (int nt = 0; nt < 4; nt++) {
                int p = nt >> 1, s = nt & 1;
                mma16816(acc[mt][nt], ah[mt], bh[p][2*s], bh[p][2*s+1]);
                mma16816(acc[mt][nt], ah[mt], bl[p][2*s], bl[p][2*s+1]);
                mma16816(acc[mt][nt], al[mt], bh[p][2*s], bh[p][2*s+1]);
            }
        }
        __syncthreads();
    }

    if (!vmode) {
#pragma unroll
        for (int mt = 0; mt < 4; mt++) {
            int r = row0 + wm * 64 + mt * 16 + (lane >> 2);
#pragma unroll
            for (int nt = 0; nt < 4; nt++) {
                int c = col0 + wn * 32 + nt * 8 + (lane & 3) * 2;
                *reinterpret_cast<float2*>(&C[(size_t)r * DIMN + c]) =
                    make_float2(acc[mt][nt][0], acc[mt][nt][1]);
                *reinterpret_cast<float2*>(&C[(size_t)(r + 8) * DIMN + c]) =
                    make_float2(acc[mt][nt][2], acc[mt][nt][3]);
            }
        }
    } else {
        // V: split to bf16 hi/lo, scatter transposed into [B,H,S,hd]
#pragma unroll
        for (int mt = 0; mt < 4; mt++) {
            int r = row0 + wm * 64 + mt * 16 + (lane >> 2);
#pragma unroll
            for (int nt = 0; nt < 4; nt++) {
                int c = col0 + wn * 32 + nt * 8 + (lane & 3) * 2;
#pragma unroll
                for (int e = 0; e < 4; e++) {
                    int rr = r + (e >> 1) * 8;
                    int cc = c + (e & 1);
                    int b = rr >> 11, s = rr & (SEQ-1);
                    int h = cc >> 6,  d = cc & (HD-1);
                    size_t di = (((size_t)(b*NH + h))*SEQ + s)*HD + d;
                    float v = acc[mt][nt][e];
                    unsigned short hb = bfbits(v);
                    unsigned short lb = bfbits(v - bf2f(hb));
                    reinterpret_cast<unsigned short*>(g_vthi)[di] = hb;
                    reinterpret_cast<unsigned short*>(g_vtlo)[di] = lb;
                }
            }
        }
    }
}

__global__ __launch_bounds__(256)
void qkv_gemm_mma(const __nv_bfloat16* __restrict__ xhi,
                  const __nv_bfloat16* __restrict__ xlo)
{
    int z = blockIdx.z;
    if (z == 0)      gemm_mma_body(xhi, xlo, g_whi[0], g_wlo[0], g_qlin, 0);
    else if (z == 1) gemm_mma_body(xhi, xlo, g_whi[1], g_wlo[1], g_klin, 0);
    else             gemm_mma_body(xhi, xlo, g_whi[2], g_wlo[2], nullptr, 1);
}

__global__ __launch_bounds__(256)
void out_gemm_mma(float* __restrict__ C)
{
    gemm_mma_body(g_ohi, g_olo, g_whi[3], g_wlo[3], C, 0);
}

// ---------------- RoPE + transpose to [B,H,S,hd], emit bf16 hi/lo -----------
__global__ void rope_transpose()
{
    int idx = blockIdx.x * blockDim.x + threadIdx.x;
    if (idx >= BATCH*SEQ*NH*(HD/2)) return;
    int d2 = idx & 31;
    int h  = (idx >> 5) & (NH-1);
    int s  = (idx >> 9) & (SEQ-1);
    int b  = idx >> 20;

    float inv = 1.0f / powf(10000.0f, (float)(2*d2) * (1.0f/(float)HD));
    float ang = (float)s * inv;
    float c  = cosf(ang);
    float sn = sinf(ang);

    size_t src = ((size_t)(b*SEQ + s))*DIMN + h*HD;
    size_t dst = (((size_t)(b*NH + h))*SEQ + s)*HD;

    float q1 = g_qlin[src + d2], q2 = g_qlin[src + d2 + 32];
    float k1 = g_klin[src + d2], k2 = g_klin[src + d2 + 32];
    float qa = q1*c - q2*sn, qb = q2*c + q1*sn;
    float ka = k1*c - k2*sn, kb = k2*c + k1*sn;

    unsigned short* qh = reinterpret_cast<unsigned short*>(g_qthi);
    unsigned short* qlp = reinterpret_cast<unsigned short*>(g_qtlo);
    unsigned short* kh = reinterpret_cast<unsigned short*>(g_kthi);
    unsigned short* klp = reinterpret_cast<unsigned short*>(g_ktlo);

    unsigned short t;
    t = bfbits(qa); qh[dst+d2] = t;      qlp[dst+d2]    = bfbits(qa - bf2f(t));
    t = bfbits(qb); qh[dst+d2+32] = t;   qlp[dst+d2+32] = bfbits(qb - bf2f(t));
    t = bfbits(ka); kh[dst+d2] = t;      klp[dst+d2]    = bfbits(ka - bf2f(t));
    t = bfbits(kb); kh[dst+d2+32] = t;   klp[dst+d2+32] = bfbits(kb - bf2f(t));
}

// ---------------- Flash attention (causal) on HMMA, split-bf16 --------------
// CTA: 128 threads = 4 warps; q-tile 64 (16 rows/warp); kv-tile 64.
// smem: sK[2 stages][2 him][64][72], sV same. Q staged through sK stage 0.
#define FROWP 72   // padded row stride in halves (conflict-free, 144B)

__device__ __forceinline__ int SKI(int st, int hm, int r) {
    return ((st*2 + hm)*64 + r) * FROWP;
}

__global__ __launch_bounds__(128)
void flash_attn_mma()
{
    const int iq = blockIdx.x, h = blockIdx.y, b = blockIdx.z;
    const int q0 = iq * 64;
    const int tid = threadIdx.x, lane = tid & 31, warp = tid >> 5;
    const float LOG2E = 1.4426950408889634f;

    extern __shared__ __align__(16) __nv_bfloat16 fsm[];
    __nv_bfloat16* sK = fsm;                       // 2*2*64*72 halves
    __nv_bfloat16* sV = fsm + 2*2*64*FROWP;

    const size_t bh = (size_t)(b*NH + h) * SEQ * HD;
    const __nv_bfloat16* Qh = g_qthi + bh + (size_t)q0*HD;
    const __nv_bfloat16* Ql = g_qtlo + bh + (size_t)q0*HD;
    const __nv_bfloat16* Kh = g_kthi + bh;
    const __nv_bfloat16* Kl = g_ktlo + bh;
    const __nv_bfloat16* Vh = g_vthi + bh;
    const __nv_bfloat16* Vl = g_vtlo + bh;

    const int lrow = tid >> 1;              // 0..63
    const int lc0  = (tid & 1) * 4;         // chunk base (x16B)

    // ---- stage Q through sK stage0, build register-resident Q fragments ----
#pragma unroll
    for (int cc = 0; cc < 4; cc++) {
        int col = (lc0 + cc) * 8;
        cp16(smem_u32(&sK[SKI(0,0,lrow) + col]), Qh + lrow*HD + col);
        cp16(smem_u32(&sK[SKI(0,1,lrow) + col]), Ql + lrow*HD + col);
    }
    cp_commit(); cp_wait0();
    __syncthreads();

    unsigned int qfh[4][4], qfl[4][4];
    {
        int r  = warp*16 + (lane & 15);
        int ch = (lane >> 4) * 8;
#pragma unroll
        for (int ks = 0; ks < 4; ks++) {
            ldmx4(smem_u32(&sK[SKI(0,0,r) + ch + ks*16]),
                  qfh[ks][0], qfh[ks][1], qfh[ks][2], qfh[ks][3]);
            ldmx4(smem_u32(&sK[SKI(0,1,r) + ch + ks*16]),
                  qfl[ks][0], qfl[ks][1], qfl[ks][2], qfl[ks][3]);
        }
    }
    __syncthreads();   // everyone done reading Q before stage0 is reused

    float oacc[8][4];
#pragma unroll
    for (int i = 0; i < 8; i++)
#pragma unroll
        for (int j = 0; j < 4; j++) oacc[i][j] = 0.0f;
    float m0 = -INFINITY, m1 = -INFINITY, l0 = 0.0f, l1 = 0.0f;

    const int nkv = iq + 1;

    // prologue: tile 0 -> stage 0
#pragma unroll
    for (int cc = 0; cc < 4; cc++) {
        int col = (lc0 + cc) * 8;
        cp16(smem_u32(&sK[SKI(0,0,lrow) + col]), Kh + lrow*HD + col);
        cp16(smem_u32(&sK[SKI(0,1,lrow) + col]), Kl + lrow*HD + col);
        cp16(smem_u32(&sV[SKI(0,0,lrow) + col]), Vh + lrow*HD + col);
        cp16(smem_u32(&sV[SKI(0,1,lrow) + col]), Vl + lrow*HD + col);
    }
    cp_commit();

    for (int t = 0; t < nkv; t++) {
        const int st = t & 1;
        if (t + 1 < nkv) {
            const int ns = (t + 1) & 1;
            const size_t go = (size_t)(t + 1) * 64 * HD;
#pragma unroll
            for (int cc = 0; cc < 4; cc++) {
                int col = (lc0 + cc) * 8;
                cp16(smem_u32(&sK[SKI(ns,0,lrow) + col]), Kh + go + lrow*HD + col);
                cp16(smem_u32(&sK[SKI(ns,1,lrow) + col]), Kl + go + lrow*HD + col);
                cp16(smem_u32(&sV[SKI(ns,0,lrow) + col]), Vh + go + lrow*HD + col);
                cp16(smem_u32(&sV[SKI(ns,1,lrow) + col]), Vl + go + lrow*HD + col);
            }
        }
        cp_commit();
        cp_wait1();
        __syncthreads();

        // ---- S = Q K^T (split, fp32 acc) ----
        float sacc[8][4];
#pragma unroll
        for (int i = 0; i < 8; i++)
#pragma unroll
            for (int j = 0; j < 4; j++) sacc[i][j] = 0.0f;

        {
            const int grp = lane >> 3;
            const int rb  = (grp >> 1) * 8 + (lane & 7);
            const int cb  = (grp & 1) * 8;
#pragma unroll
            for (int ks = 0; ks < 4; ks++) {
#pragma unroll
                for (int p = 0; p < 4; p++) {
                    unsigned int kfh[4], kfl[4];
                    ldmx4(smem_u32(&sK[SKI(st,0,p*16+rb) + cb + ks*16]),
                          kfh[0], kfh[1], kfh[2], kfh[3]);
                    ldmx4(smem_u32(&sK[SKI(st,1,p*16+rb) + cb + ks*16]),
                          kfl[0], kfl[1], kfl[2], kfl[3]);
#pragma unroll
                    for (int s = 0; s < 2; s++) {
                        int nt = 2*p + s;
                        mma16816(sacc[nt], qfh[ks], kfh[2*s], kfh[2*s+1]);
                        mma16816(sacc[nt], qfh[ks], kfl[2*s], kfl[2*s+1]);
                        mma16816(sacc[nt], qfl[ks], kfh[2*s], kfh[2*s+1]);
                    }
                }
            }
        }

        // ---- scale + causal mask (diag tile only) ----
        const int quad = lane >> 2;
        const int cpair = (lane & 3) * 2;
        if (t == nkv - 1) {
            const int r0 = q0 + warp*16 + quad;
            const int kvb = t*64 + cpair;
#pragma unroll
            for (int nt = 0; nt < 8; nt++) {
#pragma unroll
                for (int j = 0; j < 2; j++) {
                    int kg = kvb + nt*8 + j;
                    sacc[nt][j]   = (kg > r0)     ? -INFINITY : sacc[nt][j]   * 0.125f;
                    sacc[nt][2+j] = (kg > r0 + 8) ? -INFINITY : sacc[nt][2+j] * 0.125f;
                }
            }
        } else {
#pragma unroll
            for (int nt = 0; nt < 8; nt++)
#pragma unroll
                for (int j = 0; j < 4; j++) sacc[nt][j] *= 0.125f;
        }

        // ---- online softmax ----
        float mx0 = -INFINITY, mx1 = -INFINITY;
#pragma unroll
        for (int nt = 0; nt < 8; nt++) {
            mx0 = fmaxf(mx0, fmaxf(sacc[nt][0], sacc[nt][1]));
            mx1 = fmaxf(mx1, fmaxf(sacc[nt][2], sacc[nt][3]));
        }
        mx0 = fmaxf(mx0, __shfl_xor_sync(0xffffffffu, mx0, 1));
        mx0 = fmaxf(mx0, __shfl_xor_sync(0xffffffffu, mx0, 2));
        mx1 = fmaxf(mx1, __shfl_xor_sync(0xffffffffu, mx1, 1));
        mx1 = fmaxf(mx1, __shfl_xor_sync(0xffffffffu, mx1, 2));

        float mn0 = fmaxf(m0, mx0), mn1 = fmaxf(m1, mx1);
        float a0 = exp2f((m0 - mn0) * LOG2E);
        float a1 = exp2f((m1 - mn1) * LOG2E);
        m0 = mn0; m1 = mn1;

        float s0 = 0.0f, s1 = 0.0f;
#pragma unroll
        for (int nt = 0; nt < 8; nt++) {
            float p0 = exp2f((sacc[nt][0] - mn0) * LOG2E);
            float p1 = exp2f((sacc[nt][1] - mn0) * LOG2E);
            float p2 = exp2f((sacc[nt][2] - mn1) * LOG2E);
            float p3 = exp2f((sacc[nt][3] - mn1) * LOG2E);
            sacc[nt][0] = p0; sacc[nt][1] = p1; sacc[nt][2] = p2; sacc[nt][3] = p3;
            s0 += p0 + p1; s1 += p2 + p3;
        }
        s0 += __shfl_xor_sync(0xffffffffu, s0, 1);
        s0 += __shfl_xor_sync(0xffffffffu, s0, 2);
        s1 += __shfl_xor_sync(0xffffffffu, s1, 1);
        s1 += __shfl_xor_sync(0xffffffffu, s1, 2);
        l0 = l0 * a0 + s0;
        l1 = l1 * a1 + s1;

#pragma unroll
        for (int nt = 0; nt < 8; nt++) {
            oacc[nt][0] *= a0; oacc[nt][1] *= a0;
            oacc[nt][2] *= a1; oacc[nt][3] *= a1;
        }

        // ---- pack P fragments (hi/lo) ----
        unsigned int pfh[4][4], pfl[4][4];
#pragma unroll
        for (int ks = 0; ks < 4; ks++) {
#pragma unroll
            for (int half = 0; half < 2; half++) {      // rows r, r+8
                float pa = sacc[2*ks][2*half],  pb = sacc[2*ks][2*half+1];
                float pc = sacc[2*ks+1][2*half], pd = sacc[2*ks+1][2*half+1];
                unsigned short ha = bfbits(pa), hb2 = bfbits(pb);
                unsigned short hc = bfbits(pc), hd2 = bfbits(pd);
                pfh[ks][half]   = (unsigned int)ha | ((unsigned int)hb2 << 16);
                pfh[ks][2+half] = (unsigned int)hc | ((unsigned int)hd2 << 16);
                pfl[ks][half]   = pk2(pa - bf2f(ha), pb - bf2f(hb2));
                pfl[ks][2+half] = pk2(pc - bf2f(hc), pd - bf2f(hd2));
            }
        }

        // ---- O += P V (split) ----
        {
            const int g   = lane >> 3;
            const int kvr = (g & 1) * 8 + (lane & 7);
            const int dcb = (g >> 1) * 8;
#pragma unroll
            for (int dt = 0; dt < 4; dt++) {
#pragma unroll
                for (int ks = 0; ks < 4; ks++) {
                    unsigned int vfh[4], vfl[4];
                    ldmx4t(smem_u32(&sV[SKI(st,0,ks*16+kvr) + dt*16 + dcb]),
                           vfh[0], vfh[1], vfh[2], vfh[3]);
                    ldmx4t(smem_u32(&sV[SKI(st,1,ks*16+kvr) + dt*16 + dcb]),
                           vfl[0], vfl[1], vfl[2], vfl[3]);
#pragma unroll
                    for (int s = 0; s < 2; s++) {
                        int nt = 2*dt + s;
                        mma16816(oacc[nt], pfh[ks], vfh[2*s], vfh[2*s+1]);
                        mma16816(oacc[nt], pfh[ks], vfl[2*s], vfl[2*s+1]);
                        mma16816(oacc[nt], pfl[ks], vfh[2*s], vfh[2*s+1]);
                    }
                }
            }
        }
        __syncthreads();
    }

    // ---- epilogue: O/l -> g_ohi/g_olo at [B,S,D] ----
    {
        const int quad = lane >> 2;
        const int cpair = (lane & 3) * 2;
        float il0 = 1.0f / l0, il1 = 1.0f / l1;
        int r0 = q0 + warp*16 + quad;
        unsigned short* OH = reinterpret_cast<unsigned short*>(g_ohi);
        unsigned short* OL = reinterpret_cast<unsigned short*>(g_olo);
#pragma unroll
        for (int nt = 0; nt < 8; nt++) {
            int d = nt*8 + cpair;
            size_t i0 = ((size_t)(b*SEQ) + r0)     * DIMN + h*HD + d;
            size_t i1 = ((size_t)(b*SEQ) + r0 + 8) * DIMN + h*HD + d;
            float v0 = oacc[nt][0]*il0, v1 = oacc[nt][1]*il0;
            float v2 = oacc[nt][2]*il1, v3 = oacc[nt][3]*il1;
            unsigned short h0 = bfbits(v0), h1 = bfbits(v1);
            unsigned short h2 = bfbits(v2), h3 = bfbits(v3);
            *reinterpret_cast<unsigned int*>(&OH[i0]) = (unsigned)h0 | ((unsigned)h1 << 16);
            *reinterpret_cast<unsigned int*>(&OH[i1]) = (unsigned)h2 | ((unsigned)h3 << 16);
            *reinterpret_cast<unsigned int*>(&OL[i0]) =
                (unsigned)bfbits(v0 - bf2f(h0)) | ((unsigned)bfbits(v1 - bf2f(h1)) << 16);
            *reinterpret_cast<unsigned int*>(&OL[i1]) =
                (unsigned)bfbits(v2 - bf2f(h2)) | ((unsigned)bfbits(v3 - bf2f(h3)) << 16);
        }
    }
}

// ---------------- launch ----------------------------------------------------
extern "C" void kernel_launch(void* const* d_in, const int* in_sizes, int n_in,
                              void* d_out, int out_size)
{
    const float* x  = (const float*)d_in[0];
    const float* Wq = (const float*)d_in[1];
    const float* Wk = (const float*)d_in[2];
    const float* Wv = (const float*)d_in[3];
    const float* Wo = (const float*)d_in[4];
    float* out = (float*)d_out;

    __nv_bfloat16 *xhi, *xlo, *whi, *wlo;
    cudaGetSymbolAddress((void**)&xhi, g_xhi);
    cudaGetSymbolAddress((void**)&xlo, g_xlo);
    cudaGetSymbolAddress((void**)&whi, g_whi);
    cudaGetSymbolAddress((void**)&wlo, g_wlo);

    const int NW = DIMN * DIMN;
    const int NX = MROWS * DIMN;

    f32_split<<<(NX/4 + 255)/256, 256>>>(x,  xhi, xlo, NX/4);
    f32_split<<<(NW/4 + 255)/256, 256>>>(Wq, whi + 0*(size_t)NW, wlo + 0*(size_t)NW, NW/4);
    f32_split<<<(NW/4 + 255)/256, 256>>>(Wk, whi + 1*(size_t)NW, wlo + 1*(size_t)NW, NW/4);
    f32_split<<<(NW/4 + 255)/256, 256>>>(Wv, whi + 2*(size_t)NW, wlo + 2*(size_t)NW, NW/4);
    f32_split<<<(NW/4 + 255)/256, 256>>>(Wo, whi + 3*(size_t)NW, wlo + 3*(size_t)NW, NW/4);

    dim3 gqkv(DIMN/128, MROWS/128, 3);
    qkv_gemm_mma<<<gqkv, 256>>>(xhi, xlo);

    int nrope = BATCH*SEQ*NH*(HD/2);
    rope_transpose<<<(nrope + 255)/256, 256>>>();

    const int FSM_BYTES = 2 * (2*2*64*FROWP) * (int)sizeof(__nv_bfloat16);  // 73728
    cudaFuncSetAttribute(flash_attn_mma, cudaFuncAttributeMaxDynamicSharedMemorySize, FSM_BYTES);
    dim3 gfl(SEQ/64, NH, BATCH);
    flash_attn_mma<<<gfl, 128, FSM_BYTES>>>();

    dim3 gout(DIMN/128, MROWS/128);
    out_gemm_mma<<<gout, 256>>>(out);
}